// round 2
// baseline (speedup 1.0000x reference)
#include <cuda_runtime.h>
#include <math.h>

#define BATCH 4
#define HI 128
#define WI 128
#define HO 64
#define WO 64
#define DIM 128
#define NPIX_IN  (HI*WI)        // 16384
#define NPIX_OUT (HO*WO)        // 4096
#define NROWS_IN  (BATCH*NPIX_IN)   // 65536
#define NROWS_OUT (BATCH*NPIX_OUT)  // 16384

// ---------------- scratch (device globals: no allocation allowed) ----------
__device__ float g_cwT[9*DIM*DIM];                       // conv weights [tap][i][o]
__device__ float g_k   [(size_t)NROWS_IN*DIM];           // k, pixel-major
__device__ float g_v   [(size_t)NROWS_IN*DIM];           // v, pixel-major
__device__ float g_xout[(size_t)NROWS_OUT*DIM];          // running x_out
__device__ float g_q   [(size_t)NROWS_OUT*DIM];          // q per iteration
__device__ float g_h   [(size_t)NROWS_OUT*2*DIM];        // MLP hidden
__device__ float g_colsum[BATCH*NPIX_OUT];               // segment sums

// ---------------- helpers ---------------------------------------------------
static __device__ __forceinline__ float wredsum(float v){
#pragma unroll
    for (int o = 16; o > 0; o >>= 1) v += __shfl_xor_sync(0xffffffffu, v, o);
    return v;
}
static __device__ __forceinline__ float geluf(float x){
    return 0.5f * x * (1.0f + erff(x * 0.70710678118654752440f));
}

// ---------------- conv weight transpose: [o][i][kh][kw] -> [tap][i][o] ------
__global__ void transpose_cw_kernel(const float* __restrict__ cw){
    int idx = blockIdx.x * blockDim.x + threadIdx.x;
    if (idx >= 9*DIM*DIM) return;
    int o   = idx / (DIM*9);
    int rem = idx - o*(DIM*9);
    int i   = rem / 9;
    int tap = rem - i*9;
    g_cwT[(size_t)tap*DIM*DIM + i*DIM + o] = cw[idx];
}

// ---------------- generic 128x128 row projection (optional LN on input) ----
// warp-per-row; lane owns 4 consecutive outputs; weights resident in SMEM.
template<bool DO_LN>
__global__ void __launch_bounds__(128) proj128_kernel(
    const float* __restrict__ X, const float* __restrict__ W,
    const float* __restrict__ lng, const float* __restrict__ lnb,
    float* __restrict__ out)
{
    extern __shared__ float sm[];
    float* s_w   = sm;              // 16384 floats
    float* s_row = sm + DIM*DIM;    // 4*128 floats
    const int tid = threadIdx.x, warp = tid >> 5, lane = tid & 31;

#pragma unroll 8
    for (int i = tid; i < DIM*DIM; i += 128) s_w[i] = W[i];
    __syncthreads();

    const int rowBase = blockIdx.x * 64;
    for (int r = warp; r < 64; r += 4){
        const int row = rowBase + r;
        float4 xv = reinterpret_cast<const float4*>(X + (size_t)row*DIM)[lane];
        if (DO_LN){
            float mu = wredsum(xv.x+xv.y+xv.z+xv.w) * (1.0f/DIM);
            float dx = xv.x-mu, dy = xv.y-mu, dz = xv.z-mu, dw = xv.w-mu;
            float var = wredsum(dx*dx+dy*dy+dz*dz+dw*dw) * (1.0f/DIM);
            float rs = rsqrtf(var + 1e-5f);
            float4 gg = reinterpret_cast<const float4*>(lng)[lane];
            float4 bb = reinterpret_cast<const float4*>(lnb)[lane];
            xv.x = dx*rs*gg.x + bb.x;
            xv.y = dy*rs*gg.y + bb.y;
            xv.z = dz*rs*gg.z + bb.z;
            xv.w = dw*rs*gg.w + bb.w;
        }
        float* sr = s_row + warp*DIM;
        reinterpret_cast<float4*>(sr)[lane] = xv;
        __syncwarp();
        float4 acc = make_float4(0.f,0.f,0.f,0.f);
#pragma unroll 8
        for (int k = 0; k < DIM; k++){
            const float xk = sr[k];
            const float4 wk = reinterpret_cast<const float4*>(s_w + k*DIM)[lane];
            acc.x += xk*wk.x; acc.y += xk*wk.y; acc.z += xk*wk.z; acc.w += xk*wk.w;
        }
        reinterpret_cast<float4*>(out + (size_t)row*DIM)[lane] = acc;
        __syncwarp();
    }
}

// ---------------- 3x3 stride-2 conv (tap-outer) + output LayerNorm ---------
__global__ void __launch_bounds__(128) conv_ln_kernel(
    const float* __restrict__ X,
    const float* __restrict__ lng, const float* __restrict__ lnb)
{
    extern __shared__ float sm[];
    float* s_w   = sm;                      // 16384
    float* s_x   = sm + DIM*DIM;            // 32*128
    float* s_acc = sm + DIM*DIM + 32*DIM;   // 32*128
    const int tid = threadIdx.x, warp = tid >> 5, lane = tid & 31;
    const int opBase = blockIdx.x * 32;     // 32 output pixels per block (same batch)
    const int b = opBase >> 12;

#pragma unroll
    for (int i = tid; i < 32*DIM; i += 128) s_acc[i] = 0.f;

    for (int tap = 0; tap < 9; tap++){
        __syncthreads();
#pragma unroll 8
        for (int i = tid; i < DIM*DIM; i += 128)
            s_w[i] = g_cwT[(size_t)tap*DIM*DIM + i];
        const int kh = tap / 3, kw = tap % 3;
        for (int r = 0; r < 32; r++){
            const int hw = (opBase + r) & 4095;
            const int h = hw >> 6, w = hw & 63;
            const int hi = 2*h - 1 + kh, wi = 2*w - 1 + kw;
            float v = 0.f;
            if (hi >= 0 && hi < HI && wi >= 0 && wi < WI)
                v = X[((size_t)b*NPIX_IN + hi*WI + wi)*DIM + tid];
            s_x[r*DIM + tid] = v;
        }
        __syncthreads();
        for (int r = warp; r < 32; r += 4){
            float4 a = reinterpret_cast<float4*>(s_acc + r*DIM)[lane];
            const float* xr = s_x + r*DIM;
#pragma unroll 8
            for (int k = 0; k < DIM; k++){
                const float xk = xr[k];
                const float4 wk = reinterpret_cast<const float4*>(s_w + k*DIM)[lane];
                a.x += xk*wk.x; a.y += xk*wk.y; a.z += xk*wk.z; a.w += xk*wk.w;
            }
            reinterpret_cast<float4*>(s_acc + r*DIM)[lane] = a;
        }
    }
    __syncthreads();
    const float4 gg = reinterpret_cast<const float4*>(lng)[lane];
    const float4 bb = reinterpret_cast<const float4*>(lnb)[lane];
    for (int r = warp; r < 32; r += 4){
        float4 v = reinterpret_cast<float4*>(s_acc + r*DIM)[lane];
        float mu = wredsum(v.x+v.y+v.z+v.w) * (1.0f/DIM);
        float dx=v.x-mu, dy=v.y-mu, dz=v.z-mu, dw=v.w-mu;
        float var = wredsum(dx*dx+dy*dy+dz*dz+dw*dw) * (1.0f/DIM);
        float rs = rsqrtf(var + 1e-5f);
        float4 o;
        o.x = dx*rs*gg.x + bb.x; o.y = dy*rs*gg.y + bb.y;
        o.z = dz*rs*gg.z + bb.z; o.w = dw*rs*gg.w + bb.w;
        reinterpret_cast<float4*>(g_xout + (size_t)(opBase + r)*DIM)[lane] = o;
    }
}

// ---------------- zero column sums ------------------------------------------
__global__ void zero_colsum_kernel(){
    g_colsum[blockIdx.x*blockDim.x + threadIdx.x] = 0.f;
}

// ---------------- attention: scores + softmax + eps + colsum atomics -------
__global__ void attn_kernel(const float* __restrict__ rpb,
                            const float* __restrict__ tau,
                            float* __restrict__ attn_out)
{
    const int tid = threadIdx.x, warp = tid >> 5, lane = tid & 31;
    const int id  = blockIdx.x*4 + warp;     // [0, B*4*4096)
    const int b   = id >> 14;
    const int rem = id & 16383;
    const int g   = rem >> 12;
    const int hw  = rem & 4095;
    const int h = hw >> 6, w = hw & 63;
    const int ga = g >> 1, gb = g & 1;
    const int pix = (2*h + ga)*WI + 2*w + gb;
    const float4 kv = reinterpret_cast<const float4*>(g_k + ((size_t)b*NPIX_IN + pix)*DIM)[lane];
    const float scale = expf(tau[0]);
    const int ch = min(max(h,1), HO-2), cw = min(max(w,1), WO-2);

    float p[9];
    float m = -1e30f;
#pragma unroll
    for (int t = 0; t < 9; t++){
        const int nh = ch + t/3 - 1, nw = cw + t%3 - 1;
        const float4 q4 = reinterpret_cast<const float4*>(g_q + ((size_t)b*NPIX_OUT + nh*WO + nw)*DIM)[lane];
        float d = kv.x*q4.x + kv.y*q4.y + kv.z*q4.z + kv.w*q4.w;
        d = wredsum(d);
        const float val = (d + rpb[g*9 + t]) * scale;
        p[t] = val;
        m = fmaxf(m, val);
    }
    float s = 0.f;
#pragma unroll
    for (int t = 0; t < 9; t++){ p[t] = expf(p[t] - m); s += p[t]; }
    const float inv = 1.f/s;
#pragma unroll
    for (int t = 0; t < 9; t++) p[t] = p[t]*inv + 1e-6f;

    if (lane == 0){
        float* ao = attn_out + (size_t)id*9;
#pragma unroll
        for (int t = 0; t < 9; t++) ao[t] = p[t];
#pragma unroll
        for (int t = 0; t < 9; t++){
            const int nh = ch + t/3 - 1, nw = cw + t%3 - 1;
            atomicAdd(&g_colsum[b*NPIX_OUT + nh*WO + nw], p[t]);
        }
    }
}

// ---------------- normalized aggregation: A_col + upd + residual -----------
__global__ void upd_kernel(const float* __restrict__ attn_in,
                           float* __restrict__ acol_out)
{
    const int tid = threadIdx.x, warp = tid >> 5, lane = tid & 31;
    const int id = blockIdx.x*4 + warp;      // b*4096 + hw
    const int b  = id >> 12;
    const int hw = id & 4095;
    const int h = hw >> 6, w = hw & 63;
    const int ch = min(max(h,1), HO-2), cw = min(max(w,1), WO-2);

    float inv_dn[9];
#pragma unroll
    for (int t = 0; t < 9; t++){
        const int nh = ch + t/3 - 1, nw = cw + t%3 - 1;
        inv_dn[t] = 1.0f / (g_colsum[b*NPIX_OUT + nh*WO + nw] + 1e-8f);
    }
    float4 acc = make_float4(0.f,0.f,0.f,0.f);
#pragma unroll
    for (int g = 0; g < 4; g++){
        const int ga = g >> 1, gb = g & 1;
        const size_t base = ((size_t)((b*4 + g)*NPIX_OUT) + hw)*9;
        const float* ab = attn_in + base;
        float* cb = acol_out + base;
#pragma unroll
        for (int t = 0; t < 9; t++){
            const float coeff = ab[t] * inv_dn[t];
            if (lane == 0) cb[t] = coeff;
            const int nh = ch + t/3 - 1, nw = cw + t%3 - 1;
            const int pix = (2*nh + ga)*WI + 2*nw + gb;
            const float4 vv = reinterpret_cast<const float4*>(g_v + ((size_t)b*NPIX_IN + pix)*DIM)[lane];
            acc.x += coeff*vv.x; acc.y += coeff*vv.y; acc.z += coeff*vv.z; acc.w += coeff*vv.w;
        }
    }
    float4* xo = reinterpret_cast<float4*>(g_xout + (size_t)id*DIM);
    float4 v = xo[lane];
    v.x += acc.x; v.y += acc.y; v.z += acc.z; v.w += acc.w;
    xo[lane] = v;
}

// ---------------- MLP layer 1: gelu(x @ W1 + b1), N=256 (two 128 chunks) ---
__global__ void __launch_bounds__(128) mlp1_kernel(const float* __restrict__ W1,
                                                   const float* __restrict__ B1)
{
    extern __shared__ float sm[];
    float* s_w   = sm;             // 16384
    float* s_row = sm + DIM*DIM;   // 512
    const int tid = threadIdx.x, warp = tid >> 5, lane = tid & 31;
    const int rowBase = blockIdx.x * 64;

    for (int c = 0; c < 2; c++){
        __syncthreads();
#pragma unroll 8
        for (int i = tid; i < DIM*DIM; i += 128)
            s_w[i] = W1[(i >> 7)*256 + c*128 + (i & 127)];
        __syncthreads();
        const float4 bb = reinterpret_cast<const float4*>(B1 + c*128)[lane];
        for (int r = warp; r < 64; r += 4){
            const int row = rowBase + r;
            float4 xv = reinterpret_cast<const float4*>(g_xout + (size_t)row*DIM)[lane];
            float* sr = s_row + warp*DIM;
            reinterpret_cast<float4*>(sr)[lane] = xv;
            __syncwarp();
            float4 acc = bb;
#pragma unroll 8
            for (int k = 0; k < DIM; k++){
                const float xk = sr[k];
                const float4 wk = reinterpret_cast<const float4*>(s_w + k*DIM)[lane];
                acc.x += xk*wk.x; acc.y += xk*wk.y; acc.z += xk*wk.z; acc.w += xk*wk.w;
            }
            acc.x = geluf(acc.x); acc.y = geluf(acc.y);
            acc.z = geluf(acc.z); acc.w = geluf(acc.w);
            reinterpret_cast<float4*>(g_h + (size_t)row*256 + c*128)[lane] = acc;
            __syncwarp();
        }
    }
}

// ---------------- MLP layer 2 + LN + residual; optional final write --------
__global__ void __launch_bounds__(128) mlp2_kernel(
    const float* __restrict__ W2, const float* __restrict__ B2,
    const float* __restrict__ lng, const float* __restrict__ lnb,
    float* __restrict__ final_out, int writeFinal)
{
    extern __shared__ float sm[];
    float* s_w   = sm;             // 32768
    float* s_row = sm + 256*DIM;   // 4*256
    const int tid = threadIdx.x, warp = tid >> 5, lane = tid & 31;
    const int rowBase = blockIdx.x * 64;

#pragma unroll 8
    for (int i = tid; i < 256*DIM; i += 128) s_w[i] = W2[i];
    __syncthreads();
    const float4 bb2 = reinterpret_cast<const float4*>(B2)[lane];
    const float4 gg  = reinterpret_cast<const float4*>(lng)[lane];
    const float4 lb  = reinterpret_cast<const float4*>(lnb)[lane];

    for (int r = warp; r < 64; r += 4){
        const int row = rowBase + r;
        const float4* h4 = reinterpret_cast<const float4*>(g_h + (size_t)row*256);
        float* sr = s_row + warp*256;
        reinterpret_cast<float4*>(sr)[lane]      = h4[lane];
        reinterpret_cast<float4*>(sr)[lane + 32] = h4[lane + 32];
        __syncwarp();
        float4 acc = bb2;
#pragma unroll 8
        for (int k = 0; k < 256; k++){
            const float xk = sr[k];
            const float4 wk = reinterpret_cast<const float4*>(s_w + k*DIM)[lane];
            acc.x += xk*wk.x; acc.y += xk*wk.y; acc.z += xk*wk.z; acc.w += xk*wk.w;
        }
        float mu = wredsum(acc.x+acc.y+acc.z+acc.w) * (1.0f/DIM);
        float dx=acc.x-mu, dy=acc.y-mu, dz=acc.z-mu, dw=acc.w-mu;
        float var = wredsum(dx*dx+dy*dy+dz*dz+dw*dw) * (1.0f/DIM);
        float rs = rsqrtf(var + 1e-5f);
        float4 xo = reinterpret_cast<float4*>(g_xout + (size_t)row*DIM)[lane];
        xo.x += dx*rs*gg.x + lb.x;
        xo.y += dy*rs*gg.y + lb.y;
        xo.z += dz*rs*gg.z + lb.z;
        xo.w += dw*rs*gg.w + lb.w;
        reinterpret_cast<float4*>(g_xout + (size_t)row*DIM)[lane] = xo;
        if (writeFinal)
            reinterpret_cast<float4*>(final_out + (size_t)row*DIM)[lane] = xo;
        __syncwarp();
    }
}

// ---------------- launch ----------------------------------------------------
extern "C" void kernel_launch(void* const* d_in, const int* in_sizes, int n_in,
                              void* d_out, int out_size)
{
    const float* x      = (const float*)d_in[0];
    const float* convw  = (const float*)d_in[1];
    const float* q_w    = (const float*)d_in[2];
    const float* k_w    = (const float*)d_in[3];
    const float* v_w    = (const float*)d_in[4];
    const float* w1     = (const float*)d_in[5];
    const float* b1     = (const float*)d_in[6];
    const float* w2     = (const float*)d_in[7];
    const float* b2     = (const float*)d_in[8];
    const float* lin_g  = (const float*)d_in[9];
    const float* lin_b  = (const float*)d_in[10];
    const float* lout_g = (const float*)d_in[11];
    const float* lout_b = (const float*)d_in[12];
    const float* tau    = (const float*)d_in[13];
    const float* rpb    = (const float*)d_in[14];

    float* out      = (float*)d_out;
    float* out_x    = out;                                        // (4,4096,128)
    float* out_attn = out + (size_t)NROWS_OUT*DIM;                // (4,4,64,64,9)
    float* out_acol = out_attn + (size_t)BATCH*4*NPIX_OUT*9;      // (4,4,64,64,9)

    float *pk, *pv, *pq, *pxout;
    cudaGetSymbolAddress((void**)&pk,    g_k);
    cudaGetSymbolAddress((void**)&pv,    g_v);
    cudaGetSymbolAddress((void**)&pq,    g_q);
    cudaGetSymbolAddress((void**)&pxout, g_xout);

    const int SM_PROJ = (DIM*DIM + 4*DIM)        * (int)sizeof(float); // 67584
    const int SM_CONV = (DIM*DIM + 2*32*DIM)     * (int)sizeof(float); // 98304
    const int SM_MLP2 = (256*DIM + 4*256)        * (int)sizeof(float); // 135168
    cudaFuncSetAttribute(proj128_kernel<true>,  cudaFuncAttributeMaxDynamicSharedMemorySize, SM_PROJ);
    cudaFuncSetAttribute(proj128_kernel<false>, cudaFuncAttributeMaxDynamicSharedMemorySize, SM_PROJ);
    cudaFuncSetAttribute(conv_ln_kernel,        cudaFuncAttributeMaxDynamicSharedMemorySize, SM_CONV);
    cudaFuncSetAttribute(mlp1_kernel,           cudaFuncAttributeMaxDynamicSharedMemorySize, SM_PROJ);
    cudaFuncSetAttribute(mlp2_kernel,           cudaFuncAttributeMaxDynamicSharedMemorySize, SM_MLP2);

    // one-time (per launch) preprocessing
    transpose_cw_kernel<<<(9*DIM*DIM + 255)/256, 256>>>(convw);
    proj128_kernel<true ><<<NROWS_IN/64, 128, SM_PROJ>>>(x, k_w, lin_g, lin_b, pk);
    proj128_kernel<false><<<NROWS_IN/64, 128, SM_PROJ>>>(x, v_w, nullptr, nullptr, pv);
    conv_ln_kernel<<<NROWS_OUT/32, 128, SM_CONV>>>(x, lout_g, lout_b);

    for (int it = 0; it < 3; it++){
        zero_colsum_kernel<<<(BATCH*NPIX_OUT)/256, 256>>>();
        proj128_kernel<true><<<NROWS_OUT/64, 128, SM_PROJ>>>(pxout, q_w, lout_g, lout_b, pq);
        attn_kernel<<<(BATCH*4*NPIX_OUT)/4, 128>>>(rpb, tau, out_attn);
        upd_kernel<<<NROWS_OUT/4, 128>>>(out_attn, out_acol);
        mlp1_kernel<<<NROWS_OUT/64, 128, SM_PROJ>>>(w1, b1);
        mlp2_kernel<<<NROWS_OUT/64, 128, SM_MLP2>>>(w2, b2, lout_g, lout_b, out_x, it == 2 ? 1 : 0);
    }
    (void)in_sizes; (void)n_in; (void)out_size;
}

// round 4
// speedup vs baseline: 2.2740x; 2.2740x over previous
#include <cuda_runtime.h>
#include <math.h>

#define BATCH 4
#define HI 128
#define WI 128
#define HO 64
#define WO 64
#define DIM 128
#define NPIX_IN  (HI*WI)        // 16384
#define NPIX_OUT (HO*WO)        // 4096
#define NROWS_IN  (BATCH*NPIX_IN)   // 65536
#define NROWS_OUT (BATCH*NPIX_OUT)  // 16384

// ---------------- scratch (device globals) ----------------------------------
__device__ float g_cwT[9*DIM*DIM];                       // conv weights [tap][i][o]
__device__ float g_k   [(size_t)NROWS_IN*DIM];
__device__ float g_v   [(size_t)NROWS_IN*DIM];
__device__ float g_xln [(size_t)NROWS_IN*DIM];           // LN-ed activations
__device__ float g_xout[(size_t)NROWS_OUT*DIM];
__device__ float g_q   [(size_t)NROWS_OUT*DIM];
__device__ float g_h   [(size_t)NROWS_OUT*2*DIM];
__device__ float g_colsum[BATCH*NPIX_OUT];

// ---------------- helpers ----------------------------------------------------
static __device__ __forceinline__ float wredsum(float v){
#pragma unroll
    for (int o = 16; o > 0; o >>= 1) v += __shfl_xor_sync(0xffffffffu, v, o);
    return v;
}
static __device__ __forceinline__ float redsum16(float v){
#pragma unroll
    for (int o = 8; o > 0; o >>= 1) v += __shfl_xor_sync(0xffffffffu, v, o);
    return v;
}
static __device__ __forceinline__ float geluf(float x){
    return 0.5f * x * (1.0f + erff(x * 0.70710678118654752440f));
}

// ---------------- conv weight transpose: [o][i][kh][kw] -> [tap][i][o] -------
__global__ void transpose_cw_kernel(const float* __restrict__ cw){
    int idx = blockIdx.x * blockDim.x + threadIdx.x;
    if (idx >= 9*DIM*DIM) return;
    int o   = idx / (DIM*9);
    int rem = idx - o*(DIM*9);
    int i   = rem / 9;
    int tap = rem - i*9;
    g_cwT[(size_t)tap*DIM*DIM + i*DIM + o] = cw[idx];
}

// ---------------- standalone LayerNorm (warp per row) ------------------------
__global__ void __launch_bounds__(256) ln_kernel(
    const float* __restrict__ in, float* __restrict__ out,
    const float* __restrict__ g, const float* __restrict__ b)
{
    const int lane = threadIdx.x & 31, warp = threadIdx.x >> 5;
    const int row = blockIdx.x*8 + warp;
    float4 v = reinterpret_cast<const float4*>(in + (size_t)row*DIM)[lane];
    float mu = wredsum(v.x+v.y+v.z+v.w) * (1.0f/DIM);
    float dx=v.x-mu, dy=v.y-mu, dz=v.z-mu, dw=v.w-mu;
    float var = wredsum(dx*dx+dy*dy+dz*dz+dw*dw) * (1.0f/DIM);
    float rs = rsqrtf(var + 1e-5f);
    float4 gg = reinterpret_cast<const float4*>(g)[lane];
    float4 bb = reinterpret_cast<const float4*>(b)[lane];
    float4 o;
    o.x = dx*rs*gg.x + bb.x; o.y = dy*rs*gg.y + bb.y;
    o.z = dz*rs*gg.z + bb.z; o.w = dw*rs*gg.w + bb.w;
    reinterpret_cast<float4*>(out + (size_t)row*DIM)[lane] = o;
}

// ---------------- register-tiled SGEMM: C[M,128] = A[M,K] @ B[K,*] -----------
// 256 threads, 128x128 block tile, 8x8 micro-tile, K-chunks of 32.
#define EPI_STORE 0
#define EPI_GELU  1
#define EPI_LNRES 2

__global__ void __launch_bounds__(256,2) gemm_kernel(
    const float* __restrict__ A, int K,
    const float* __restrict__ B, int ldb,
    const float* __restrict__ bias,
    const float* __restrict__ lng, const float* __restrict__ lnb,
    float* __restrict__ C, int ldc,
    float* __restrict__ res, float* __restrict__ fin,
    int epi, int writeFinal)
{
    __shared__ __align__(16) float As[32*132];
    __shared__ __align__(16) float Bs[32*128];
    const int tid = threadIdx.x;
    const int tx = tid & 15, ty = tid >> 4;
    const int mBase = blockIdx.x * 128;
    const int col0  = blockIdx.y * 128;

    float acc[8][8];
#pragma unroll
    for (int r = 0; r < 8; r++)
#pragma unroll
        for (int c = 0; c < 8; c++) acc[r][c] = 0.f;

    for (int k0 = 0; k0 < K; k0 += 32){
#pragma unroll
        for (int i = 0; i < 4; i++){
            int idx = tid + i*256;
            int m = idx & 127, q = idx >> 7;
            float4 a = *reinterpret_cast<const float4*>(A + (size_t)(mBase+m)*K + k0 + q*4);
            As[(q*4+0)*132 + m] = a.x;
            As[(q*4+1)*132 + m] = a.y;
            As[(q*4+2)*132 + m] = a.z;
            As[(q*4+3)*132 + m] = a.w;
        }
#pragma unroll
        for (int i = 0; i < 4; i++){
            int idx = tid + i*256;
            int c4 = idx & 31, kk = idx >> 5;
            *reinterpret_cast<float4*>(Bs + kk*128 + c4*4) =
                *reinterpret_cast<const float4*>(B + (size_t)(k0+kk)*ldb + col0 + c4*4);
        }
        __syncthreads();
#pragma unroll 8
        for (int k = 0; k < 32; k++){
            float4 a0 = *reinterpret_cast<float4*>(As + k*132 + ty*8);
            float4 a1 = *reinterpret_cast<float4*>(As + k*132 + ty*8 + 4);
            float4 b0 = *reinterpret_cast<float4*>(Bs + k*128 + tx*8);
            float4 b1 = *reinterpret_cast<float4*>(Bs + k*128 + tx*8 + 4);
            float av[8] = {a0.x,a0.y,a0.z,a0.w,a1.x,a1.y,a1.z,a1.w};
            float bv[8] = {b0.x,b0.y,b0.z,b0.w,b1.x,b1.y,b1.z,b1.w};
#pragma unroll
            for (int r = 0; r < 8; r++)
#pragma unroll
                for (int c = 0; c < 8; c++)
                    acc[r][c] += av[r]*bv[c];
        }
        __syncthreads();
    }

    const int row0 = mBase + ty*8;
    const int c0   = col0 + tx*8;

    if (epi == EPI_STORE){
#pragma unroll
        for (int r = 0; r < 8; r++){
            float4* cp = reinterpret_cast<float4*>(C + (size_t)(row0+r)*ldc + c0);
            cp[0] = make_float4(acc[r][0],acc[r][1],acc[r][2],acc[r][3]);
            cp[1] = make_float4(acc[r][4],acc[r][5],acc[r][6],acc[r][7]);
        }
    } else if (epi == EPI_GELU){
        float bb[8];
#pragma unroll
        for (int c = 0; c < 8; c++) bb[c] = bias[c0+c];
#pragma unroll
        for (int r = 0; r < 8; r++){
            float v[8];
#pragma unroll
            for (int c = 0; c < 8; c++) v[c] = geluf(acc[r][c] + bb[c]);
            float4* cp = reinterpret_cast<float4*>(C + (size_t)(row0+r)*ldc + c0);
            cp[0] = make_float4(v[0],v[1],v[2],v[3]);
            cp[1] = make_float4(v[4],v[5],v[6],v[7]);
        }
    } else { // EPI_LNRES: x_out += LN(acc + bias)
        float bb[8], gg[8], be[8];
#pragma unroll
        for (int c = 0; c < 8; c++){
            bb[c] = bias[c0+c]; gg[c] = lng[c0+c]; be[c] = lnb[c0+c];
        }
#pragma unroll
        for (int r = 0; r < 8; r++){
            float v[8]; float s = 0.f;
#pragma unroll
            for (int c = 0; c < 8; c++){ v[c] = acc[r][c] + bb[c]; s += v[c]; }
            s = redsum16(s);
            float mu = s * (1.0f/128.0f);
            float s2 = 0.f;
#pragma unroll
            for (int c = 0; c < 8; c++){ v[c] -= mu; s2 += v[c]*v[c]; }
            s2 = redsum16(s2);
            float rs = rsqrtf(s2*(1.0f/128.0f) + 1e-5f);
            float* rp = res + (size_t)(row0+r)*DIM + c0;
            float o[8];
#pragma unroll
            for (int c = 0; c < 8; c++) o[c] = rp[c] + v[c]*rs*gg[c] + be[c];
            reinterpret_cast<float4*>(rp)[0] = make_float4(o[0],o[1],o[2],o[3]);
            reinterpret_cast<float4*>(rp)[1] = make_float4(o[4],o[5],o[6],o[7]);
            if (writeFinal){
                float* fp = fin + (size_t)(row0+r)*DIM + c0;
                reinterpret_cast<float4*>(fp)[0] = make_float4(o[0],o[1],o[2],o[3]);
                reinterpret_cast<float4*>(fp)[1] = make_float4(o[4],o[5],o[6],o[7]);
            }
        }
    }
}

// ---------------- conv as tap-looped SGEMM + LN epilogue ---------------------
// 64 out-pixels x 128 out-channels per block; 256 threads; 4x8 micro-tile.
__global__ void __launch_bounds__(256) conv_kernel(
    const float* __restrict__ X,
    const float* __restrict__ lng, const float* __restrict__ lnb)
{
    __shared__ __align__(16) float As[32*68];
    __shared__ __align__(16) float Bs[32*128];
    const int tid = threadIdx.x;
    const int tx = tid & 15, ty = tid >> 4;
    const int base = blockIdx.x * 64;     // out-pixel base (same batch)
    const int b = base >> 12;

    float acc[4][8];
#pragma unroll
    for (int r = 0; r < 4; r++)
#pragma unroll
        for (int c = 0; c < 8; c++) acc[r][c] = 0.f;

    for (int ch = 0; ch < 36; ch++){
        const int tap = ch >> 2;
        const int k0  = (ch & 3) * 32;
        const int kh = tap/3 - 1, kw = tap%3 - 1;
#pragma unroll
        for (int i = 0; i < 2; i++){
            int idx = tid + i*256;
            int m = idx & 63, q = idx >> 6;
            int hw = (base + m) & 4095;
            int h = hw >> 6, w = hw & 63;
            int hi = 2*h + kh, wi = 2*w + kw;
            float4 a = make_float4(0.f,0.f,0.f,0.f);
            if ((unsigned)hi < HI && (unsigned)wi < WI)
                a = *reinterpret_cast<const float4*>(
                      X + ((size_t)b*NPIX_IN + hi*WI + wi)*DIM + k0 + q*4);
            As[(q*4+0)*68 + m] = a.x;
            As[(q*4+1)*68 + m] = a.y;
            As[(q*4+2)*68 + m] = a.z;
            As[(q*4+3)*68 + m] = a.w;
        }
#pragma unroll
        for (int i = 0; i < 4; i++){
            int idx = tid + i*256;
            int c4 = idx & 31, kk = idx >> 5;
            *reinterpret_cast<float4*>(Bs + kk*128 + c4*4) =
                *reinterpret_cast<const float4*>(g_cwT + (size_t)tap*DIM*DIM + (k0+kk)*128 + c4*4);
        }
        __syncthreads();
#pragma unroll 8
        for (int k = 0; k < 32; k++){
            float4 a0 = *reinterpret_cast<float4*>(As + k*68 + ty*4);
            float4 b0 = *reinterpret_cast<float4*>(Bs + k*128 + tx*8);
            float4 b1 = *reinterpret_cast<float4*>(Bs + k*128 + tx*8 + 4);
            float av[4] = {a0.x,a0.y,a0.z,a0.w};
            float bv[8] = {b0.x,b0.y,b0.z,b0.w,b1.x,b1.y,b1.z,b1.w};
#pragma unroll
            for (int r = 0; r < 4; r++)
#pragma unroll
                for (int c = 0; c < 8; c++)
                    acc[r][c] += av[r]*bv[c];
        }
        __syncthreads();
    }

    // LN epilogue -> g_xout
    const int row0 = base + ty*4;
    const int c0 = tx*8;
    float gg[8], be[8];
#pragma unroll
    for (int c = 0; c < 8; c++){ gg[c] = lng[c0+c]; be[c] = lnb[c0+c]; }
#pragma unroll
    for (int r = 0; r < 4; r++){
        float v[8]; float s = 0.f;
#pragma unroll
        for (int c = 0; c < 8; c++){ v[c] = acc[r][c]; s += v[c]; }
        s = redsum16(s);
        float mu = s * (1.0f/128.0f);
        float s2 = 0.f;
#pragma unroll
        for (int c = 0; c < 8; c++){ v[c] -= mu; s2 += v[c]*v[c]; }
        s2 = redsum16(s2);
        float rs = rsqrtf(s2*(1.0f/128.0f) + 1e-5f);
        float* op = g_xout + (size_t)(row0+r)*DIM + c0;
        reinterpret_cast<float4*>(op)[0] = make_float4(
            v[0]*rs*gg[0]+be[0], v[1]*rs*gg[1]+be[1], v[2]*rs*gg[2]+be[2], v[3]*rs*gg[3]+be[3]);
        reinterpret_cast<float4*>(op)[1] = make_float4(
            v[4]*rs*gg[4]+be[4], v[5]*rs*gg[5]+be[5], v[6]*rs*gg[6]+be[6], v[7]*rs*gg[7]+be[7]);
    }
}

// ---------------- zero column sums -------------------------------------------
__global__ void zero_colsum_kernel(){
    g_colsum[blockIdx.x*blockDim.x + threadIdx.x] = 0.f;
}

// ---------------- attention: scores + softmax + eps + colsum atomics ---------
__global__ void attn_kernel(const float* __restrict__ rpb,
                            const float* __restrict__ tau,
                            float* __restrict__ attn_out)
{
    const int tid = threadIdx.x, warp = tid >> 5, lane = tid & 31;
    const int id  = blockIdx.x*4 + warp;
    const int b   = id >> 14;
    const int rem = id & 16383;
    const int g   = rem >> 12;
    const int hw  = rem & 4095;
    const int h = hw >> 6, w = hw & 63;
    const int ga = g >> 1, gb = g & 1;
    const int pix = (2*h + ga)*WI + 2*w + gb;
    const float4 kv = reinterpret_cast<const float4*>(g_k + ((size_t)b*NPIX_IN + pix)*DIM)[lane];
    const float scale = expf(tau[0]);
    const int ch = min(max(h,1), HO-2), cw = min(max(w,1), WO-2);

    float p[9];
    float m = -1e30f;
#pragma unroll
    for (int t = 0; t < 9; t++){
        const int nh = ch + t/3 - 1, nw = cw + t%3 - 1;
        const float4 q4 = reinterpret_cast<const float4*>(g_q + ((size_t)b*NPIX_OUT + nh*WO + nw)*DIM)[lane];
        float d = kv.x*q4.x + kv.y*q4.y + kv.z*q4.z + kv.w*q4.w;
        d = wredsum(d);
        const float val = (d + rpb[g*9 + t]) * scale;
        p[t] = val;
        m = fmaxf(m, val);
    }
    float s = 0.f;
#pragma unroll
    for (int t = 0; t < 9; t++){ p[t] = expf(p[t] - m); s += p[t]; }
    const float inv = 1.f/s;
#pragma unroll
    for (int t = 0; t < 9; t++) p[t] = p[t]*inv + 1e-6f;

    if (lane == 0){
        float* ao = attn_out + (size_t)id*9;
#pragma unroll
        for (int t = 0; t < 9; t++) ao[t] = p[t];
#pragma unroll
        for (int t = 0; t < 9; t++){
            const int nh = ch + t/3 - 1, nw = cw + t%3 - 1;
            atomicAdd(&g_colsum[b*NPIX_OUT + nh*WO + nw], p[t]);
        }
    }
}

// ---------------- normalized aggregation: A_col + upd + residual -------------
__global__ void upd_kernel(const float* __restrict__ attn_in,
                           float* __restrict__ acol_out)
{
    const int tid = threadIdx.x, warp = tid >> 5, lane = tid & 31;
    const int id = blockIdx.x*4 + warp;
    const int b  = id >> 12;
    const int hw = id & 4095;
    const int h = hw >> 6, w = hw & 63;
    const int ch = min(max(h,1), HO-2), cw = min(max(w,1), WO-2);

    float inv_dn[9];
#pragma unroll
    for (int t = 0; t < 9; t++){
        const int nh = ch + t/3 - 1, nw = cw + t%3 - 1;
        inv_dn[t] = 1.0f / (g_colsum[b*NPIX_OUT + nh*WO + nw] + 1e-8f);
    }
    float4 acc = make_float4(0.f,0.f,0.f,0.f);
#pragma unroll
    for (int g = 0; g < 4; g++){
        const int ga = g >> 1, gb = g & 1;
        const size_t base = ((size_t)((b*4 + g)*NPIX_OUT) + hw)*9;
        const float* ab = attn_in + base;
        float* cb = acol_out + base;
#pragma unroll
        for (int t = 0; t < 9; t++){
            const float coeff = ab[t] * inv_dn[t];
            if (lane == 0) cb[t] = coeff;
            const int nh = ch + t/3 - 1, nw = cw + t%3 - 1;
            const int pix = (2*nh + ga)*WI + 2*nw + gb;
            const float4 vv = reinterpret_cast<const float4*>(g_v + ((size_t)b*NPIX_IN + pix)*DIM)[lane];
            acc.x += coeff*vv.x; acc.y += coeff*vv.y; acc.z += coeff*vv.z; acc.w += coeff*vv.w;
        }
    }
    float4* xo = reinterpret_cast<float4*>(g_xout + (size_t)id*DIM);
    float4 v = xo[lane];
    v.x += acc.x; v.y += acc.y; v.z += acc.z; v.w += acc.w;
    xo[lane] = v;
}

// ---------------- launch ------------------------------------------------------
extern "C" void kernel_launch(void* const* d_in, const int* in_sizes, int n_in,
                              void* d_out, int out_size)
{
    const float* x      = (const float*)d_in[0];
    const float* convw  = (const float*)d_in[1];
    const float* q_w    = (const float*)d_in[2];
    const float* k_w    = (const float*)d_in[3];
    const float* v_w    = (const float*)d_in[4];
    const float* w1     = (const float*)d_in[5];
    const float* b1     = (const float*)d_in[6];
    const float* w2     = (const float*)d_in[7];
    const float* b2     = (const float*)d_in[8];
    const float* lin_g  = (const float*)d_in[9];
    const float* lin_b  = (const float*)d_in[10];
    const float* lout_g = (const float*)d_in[11];
    const float* lout_b = (const float*)d_in[12];
    const float* tau    = (const float*)d_in[13];
    const float* rpb    = (const float*)d_in[14];

    float* out      = (float*)d_out;
    float* out_x    = out;                                        // (4,4096,128)
    float* out_attn = out + (size_t)NROWS_OUT*DIM;                // (4,4,64,64,9)
    float* out_acol = out_attn + (size_t)BATCH*4*NPIX_OUT*9;      // (4,4,64,64,9)

    float *pk, *pv, *pq, *pxout, *pxln, *ph;
    cudaGetSymbolAddress((void**)&pk,    g_k);
    cudaGetSymbolAddress((void**)&pv,    g_v);
    cudaGetSymbolAddress((void**)&pq,    g_q);
    cudaGetSymbolAddress((void**)&pxout, g_xout);
    cudaGetSymbolAddress((void**)&pxln,  g_xln);
    cudaGetSymbolAddress((void**)&ph,    g_h);

    // preprocessing
    transpose_cw_kernel<<<(9*DIM*DIM + 255)/256, 256>>>(convw);
    ln_kernel<<<NROWS_IN/8, 256>>>(x, pxln, lin_g, lin_b);
    gemm_kernel<<<NROWS_IN/128, 256>>>(pxln, 128, k_w, 128, nullptr, nullptr, nullptr,
                                       pk, 128, nullptr, nullptr, EPI_STORE, 0);
    gemm_kernel<<<NROWS_IN/128, 256>>>(x,    128, v_w, 128, nullptr, nullptr, nullptr,
                                       pv, 128, nullptr, nullptr, EPI_STORE, 0);
    conv_kernel<<<NROWS_OUT/64, 256>>>(x, lout_g, lout_b);

    for (int it = 0; it < 3; it++){
        zero_colsum_kernel<<<(BATCH*NPIX_OUT)/256, 256>>>();
        ln_kernel<<<NROWS_OUT/8, 256>>>(pxout, pxln, lout_g, lout_b);
        gemm_kernel<<<NROWS_OUT/128, 256>>>(pxln, 128, q_w, 128, nullptr, nullptr, nullptr,
                                            pq, 128, nullptr, nullptr, EPI_STORE, 0);
        attn_kernel<<<(BATCH*4*NPIX_OUT)/4, 128>>>(rpb, tau, out_attn);
        upd_kernel<<<NROWS_OUT/4, 128>>>(out_attn, out_acol);
        gemm_kernel<<<dim3(NROWS_OUT/128, 2), 256>>>(pxout, 128, w1, 256, b1, nullptr, nullptr,
                                                     ph, 256, nullptr, nullptr, EPI_GELU, 0);
        gemm_kernel<<<NROWS_OUT/128, 256>>>(ph, 256, w2, 128, b2, lout_g, lout_b,
                                            nullptr, 128, pxout, out_x, EPI_LNRES, it == 2 ? 1 : 0);
    }
    (void)in_sizes; (void)n_in; (void)out_size;
}